// round 14
// baseline (speedup 1.0000x reference)
#include <cuda_runtime.h>
#include <cuda_fp16.h>
#include <math.h>

#define Bz 512
#define Tz 128
#define Vz 64
#define Ez 256
#define Hz 512
#define Lz 128
#define G4z 2048
#define ELz 384
#define LDA 72
#define LDB 72
#define LDK 136   // row stride (halves) for 128-col step tiles; conflict-free

// ---------------- scratch ----------------
__device__ __align__(16) __half g_h[2][2 * Bz * Hz];
__device__ __align__(16) float  g_c[2 * Bz * Hz];
__device__ __align__(16) float  g_htmp[Bz * Hz];
__device__ __align__(16) float  g_hcat[Bz * 2 * Hz];
__device__ __align__(16) float  g_z[Bz * Lz];
__device__ __align__(16) float  g_zp[Bz * G4z];
__device__ __align__(16) __half g_hs[(size_t)Tz * Bz * Hz];
__device__ __align__(16) float  g_EF[Vz * G4z];
__device__ __align__(16) float  g_EB[Vz * G4z];
__device__ __align__(16) float  g_ED[Vz * G4z];
__device__ __align__(16) __half g_Uf[G4z * Hz];
__device__ __align__(16) __half g_Ub[G4z * Hz];
__device__ __align__(16) __half g_Ud[G4z * Hz];
__device__ __align__(16) __half g_Wo[Vz * Hz];

__device__ __forceinline__ float sigm(float x) { return 1.0f / (1.0f + expf(-x)); }

__device__ __forceinline__ void mma16816(float* d, const unsigned* a, unsigned b0, unsigned b1) {
    asm volatile("mma.sync.aligned.m16n8k16.row.col.f32.f16.f16.f32 "
                 "{%0,%1,%2,%3},{%4,%5,%6,%7},{%8,%9},{%0,%1,%2,%3};"
                 : "+f"(d[0]), "+f"(d[1]), "+f"(d[2]), "+f"(d[3])
                 : "r"(a[0]), "r"(a[1]), "r"(a[2]), "r"(a[3]), "r"(b0), "r"(b1));
}
__device__ __forceinline__ unsigned su(const void* p) {
    return (unsigned)__cvta_generic_to_shared(p);
}
__device__ __forceinline__ void cpa16(void* dst, const void* src) {
    asm volatile("cp.async.cg.shared.global [%0], [%1], 16;" :: "r"(su(dst)), "l"(src));
}
#define CP_COMMIT() asm volatile("cp.async.commit_group;")
#define CP_WAIT0()  asm volatile("cp.async.wait_group 0;")

// unified step: 2 stages x {A: 64xLDK, B: 128xLDK} -> 2 CTAs/SM possible
#define SMEM_S (2 * (192 * LDK) * 2)    // 104448 B
#define SMEM_OUT ((64*LDA + 64*LDB) * 2)
extern __shared__ __half smh[];

__device__ __forceinline__ void load_afrag(unsigned* f, const __half* A, int rbase) {
    f[0] = *(const unsigned*)(A + rbase);
    f[1] = *(const unsigned*)(A + rbase + 8 * LDA);
    f[2] = *(const unsigned*)(A + rbase + 8);
    f[3] = *(const unsigned*)(A + rbase + 8 * LDA + 8);
}
__device__ __forceinline__ void load_afragK(unsigned* f, const __half* A, int rbase) {
    f[0] = *(const unsigned*)(A + rbase);
    f[1] = *(const unsigned*)(A + rbase + 8 * LDK);
    f[2] = *(const unsigned*)(A + rbase + 8);
    f[3] = *(const unsigned*)(A + rbase + 8 * LDK + 8);
}

// ---------------- fused prologue kernels ----------------
__global__ void k_cvt_all(const float* __restrict__ wf, const float* __restrict__ wb,
                          const float* __restrict__ wd, const float* __restrict__ wo) {
    const int NU = G4z * Hz;
    const int NT = 3 * NU + Vz * Hz;
    int i = blockIdx.x * blockDim.x + threadIdx.x;
    for (; i < NT; i += gridDim.x * blockDim.x) {
        if (i < NU)               g_Uf[i] = __float2half_rn(wf[i]);
        else if (i < 2 * NU)      g_Ub[i - NU] = __float2half_rn(wb[i - NU]);
        else if (i < 3 * NU)      g_Ud[i - 2 * NU] = __float2half_rn(wd[i - 2 * NU]);
        else                      g_Wo[i - 3 * NU] = __float2half_rn(wo[i - 3 * NU]);
    }
}
__global__ void k_zero_state() {
    int i = blockIdx.x * blockDim.x + threadIdx.x;
    if (i < 2 * Bz * Hz) {
        __half zz = __float2half(0.f);
        g_h[0][i] = zz; g_h[1][i] = zz; g_c[i] = 0.f;
    }
}
__global__ void k_hd_init() {
    int i = blockIdx.x * blockDim.x + threadIdx.x;
    if (i < Bz * Hz) { g_h[0][i] = __float2half_rn(g_htmp[i]); g_c[i] = 0.f; }
}
__global__ void k_copy_hcat() {
    int i = blockIdx.x * blockDim.x + threadIdx.x;
    if (i < 2 * Bz * Hz) {
        int s = i >> 9;
        int j = i & (Hz - 1);
        int b = s & (Bz - 1);
        int dir = s >> 9;
        g_hcat[b * (2 * Hz) + dir * Hz + j] = __half2float(g_h[0][i]);
    }
}
__global__ void k_reparam(const float* __restrict__ eps, const float* __restrict__ muv,
                          const float* __restrict__ lvv) {
    int i = blockIdx.x * blockDim.x + threadIdx.x;
    if (i < Bz * Lz) g_z[i] = muv[i] + eps[i] * expf(0.5f * lvv[i]);
}

// ---------------- fp32 GEMM body (shared) ----------------
__device__ __forceinline__ void gemm_body(int K,
                                          const float* __restrict__ A, int lda,
                                          const float* __restrict__ Bw, int ldb,
                                          const float* __restrict__ bias,
                                          float* __restrict__ C, int ldc,
                                          int m0, int n0) {
    __shared__ float As[16][68];
    __shared__ float Bs[16][68];
    const int tid = threadIdx.x;
    const int lr = tid >> 2, lk = tid & 3;
    const int tx = tid & 15, ty = tid >> 4;
    float acc[4][4] = {};
    for (int k0 = 0; k0 < K; k0 += 16) {
        float4 av = *(const float4*)(A + (size_t)(m0 + lr) * lda + k0 + lk * 4);
        float4 bv = *(const float4*)(Bw + (size_t)(n0 + lr) * ldb + k0 + lk * 4);
        __syncthreads();
        As[lk*4+0][lr]=av.x; As[lk*4+1][lr]=av.y; As[lk*4+2][lr]=av.z; As[lk*4+3][lr]=av.w;
        Bs[lk*4+0][lr]=bv.x; Bs[lk*4+1][lr]=bv.y; Bs[lk*4+2][lr]=bv.z; Bs[lk*4+3][lr]=bv.w;
        __syncthreads();
#pragma unroll
        for (int k = 0; k < 16; k++) {
            float4 a = *(const float4*)&As[k][ty*4];
            float4 b = *(const float4*)&Bs[k][tx*4];
            acc[0][0]+=a.x*b.x; acc[0][1]+=a.x*b.y; acc[0][2]+=a.x*b.z; acc[0][3]+=a.x*b.w;
            acc[1][0]+=a.y*b.x; acc[1][1]+=a.y*b.y; acc[1][2]+=a.y*b.z; acc[1][3]+=a.y*b.w;
            acc[2][0]+=a.z*b.x; acc[2][1]+=a.z*b.y; acc[2][2]+=a.z*b.z; acc[2][3]+=a.z*b.w;
            acc[3][0]+=a.w*b.x; acc[3][1]+=a.w*b.y; acc[3][2]+=a.w*b.z; acc[3][3]+=a.w*b.w;
        }
    }
#pragma unroll
    for (int i = 0; i < 4; i++)
#pragma unroll
        for (int j = 0; j < 4; j++) {
            int n = n0 + tx * 4 + j;
            float bb = bias ? bias[n] : 0.0f;
            C[(size_t)(m0 + ty * 4 + i) * ldc + n] = acc[i][j] + bb;
        }
}
__global__ __launch_bounds__(256) void k_gemm(int K,
                                              const float* __restrict__ A, int lda,
                                              const float* __restrict__ Bw, int ldb,
                                              const float* __restrict__ bias,
                                              float* __restrict__ C, int ldc) {
    gemm_body(K, A, lda, Bw, ldb, bias, C, ldc, blockIdx.y * 64, blockIdx.x * 64);
}
__global__ __launch_bounds__(256) void k_tables(const float* __restrict__ emb,
                                                const float* __restrict__ Wf,
                                                const float* __restrict__ bf,
                                                const float* __restrict__ Wb,
                                                const float* __restrict__ bb,
                                                const float* __restrict__ Wd,
                                                const float* __restrict__ bd) {
    int tbl = blockIdx.y;
    const float* W = (tbl == 0) ? Wf : (tbl == 1) ? Wb : Wd;
    const float* bi = (tbl == 0) ? bf : (tbl == 1) ? bb : bd;
    float* C = (tbl == 0) ? g_EF : (tbl == 1) ? g_EB : g_ED;
    int ldb = (tbl == 2) ? ELz : Ez;
    gemm_body(Ez, emb, Ez, W, ldb, bi, C, G4z, 0, blockIdx.x * 64);
}

// =============================================================================
// Unified step kernel: BM=64, K-chunk 128, 2-stage, 512 threads (16 warps,
// 4m x 4n, warp tile 16x32). __launch_bounds__(512,2) -> 2 CTAs/SM when the
// grid provides them (encoder: 256 CTAs). Direction via blockIdx.y.
// =============================================================================
__global__ __launch_bounds__(512, 2) void k_steph(int t, int pin, int ybits,
                                                  const __half* __restrict__ Ua,
                                                  const __half* __restrict__ Ub,
                                                  const int* __restrict__ ids,
                                                  const float* __restrict__ Ea,
                                                  const float* __restrict__ Eb,
                                                  int use_zp, int store_hs) {
    __shared__ int toks[64];
    const int tid = threadIdx.x;
    const int by = blockIdx.y;
    const int dir = by >> ybits;               // encoder: ybits=3; decoder: ybits=3, by<8 -> 0
    const int b0 = (by & ((1 << ybits) - 1)) * 64;
    const int sb0 = dir * Bz + b0;
    const int j0 = blockIdx.x * 32;
    const __half* U1 = dir ? Ub : Ua;
    const float*  E  = dir ? Eb : Ea;
    const __half* h1 = g_h[pin];
    const int lane = tid & 31, warp = tid >> 5;
    const int wm = warp >> 2, wn = warp & 3;
    const int g = lane >> 2, i2 = (lane & 3) * 2;

    if (tid < 64) {
        int tt = dir ? (Tz - 1 - t) : t;
        toks[tid] = ids[(b0 + tid) * Tz + tt];
    }

    __half* Abase = smh;                 // [stage][64][LDK]
    __half* Bbase = smh + 2 * 64 * LDK;  // [stage][128][LDK]
#define A_ST(st) (Abase + (st) * 64 * LDK)
#define B_ST(st) (Bbase + (st) * 128 * LDK)

    auto stage_load = [&](int st, int k0) {
#pragma unroll
        for (int it = 0; it < 2; it++) {
            int c = tid + it * 512, r = c >> 4, kc8 = c & 15;
            cpa16(A_ST(st) + r * LDK + kc8 * 8, h1 + (size_t)(sb0 + r) * Hz + k0 + kc8 * 8);
        }
#pragma unroll
        for (int it = 0; it < 4; it++) {
            int c = tid + it * 512, r = c >> 4, kc8 = c & 15;
            int q = (r >> 3) & 3, wnr = r >> 5, s = r & 7;
            size_t goff = (size_t)(q * Hz + j0 + wnr * 8 + s) * Hz + k0 + kc8 * 8;
            cpa16(B_ST(st) + r * LDK + kc8 * 8, U1 + goff);
        }
    };

    float acc[4][4] = {};
    stage_load(0, 0);
    CP_COMMIT();

    for (int kc = 0; kc < 4; kc++) {
        CP_WAIT0();
        __syncthreads();
        if (kc < 3) {
            stage_load((kc + 1) & 1, (kc + 1) * 128);
            CP_COMMIT();
        }
        const __half* A1 = A_ST(kc & 1);
        const __half* B1 = B_ST(kc & 1);
#pragma unroll
        for (int kk = 0; kk < 8; kk++) {
            int k = kk * 16;
            unsigned a1f[4], b1f[4][2];
            load_afragK(a1f, A1, (wm * 16 + g) * LDK + k + i2);
#pragma unroll
            for (int q = 0; q < 4; q++) {
                int rb = (wn * 32 + q * 8 + g) * LDK + k + i2;
                b1f[q][0] = *(const unsigned*)(B1 + rb);
                b1f[q][1] = *(const unsigned*)(B1 + rb + 8);
            }
#pragma unroll
            for (int q = 0; q < 4; q++)
                mma16816(acc[q], a1f, b1f[q][0], b1f[q][1]);
        }
    }

    __half* o1 = g_h[pin ^ 1];
    const int jb = j0 + wn * 8 + i2;
#pragma unroll
    for (int rs = 0; rs < 2; rs++) {
        int r = wm * 16 + g + rs * 8;
        int b = b0 + r;
        int sb = sb0 + r;
        int tok = toks[r];
        float2 gv[4];
#pragma unroll
        for (int q = 0; q < 4; q++) {
            int n = q * Hz + jb;
            float2 e = *(const float2*)&E[(size_t)tok * G4z + n];
            if (use_zp) {
                float2 zp2 = *(const float2*)&g_zp[(size_t)b * G4z + n];
                e.x += zp2.x; e.y += zp2.y;
            }
            gv[q] = make_float2(acc[q][rs * 2 + 0] + e.x, acc[q][rs * 2 + 1] + e.y);
        }
        int idx = sb * Hz + jb;
        float2 cold = *(const float2*)&g_c[idx];
        float cn0 = sigm(gv[1].x) * cold.x + sigm(gv[0].x) * tanhf(gv[2].x);
        float cn1 = sigm(gv[1].y) * cold.y + sigm(gv[0].y) * tanhf(gv[2].y);
        float hn0 = sigm(gv[3].x) * tanhf(cn0);
        float hn1 = sigm(gv[3].y) * tanhf(cn1);
        *(float2*)&g_c[idx] = make_float2(cn0, cn1);
        __half2 hp = __halves2half2(__float2half_rn(hn0), __float2half_rn(hn1));
        *(__half2*)&o1[idx] = hp;
        if (store_hs)
            *(__half2*)&g_hs[((size_t)t * Bz + b) * Hz + jb] = hp;
    }
#undef A_ST
#undef B_ST
}

// ---------------- output head: 1-MMA mma.sync (R10-proven) ----------------
__global__ __launch_bounds__(256) void k_outheadh(const float* __restrict__ bout,
                                                  float* __restrict__ out) {
    __half* A1 = smh;
    __half* B1 = smh + 64 * LDA;
    const int tid = threadIdx.x;
    const int m0 = blockIdx.x * 64;
    const int lane = tid & 31, warp = tid >> 5;
    const int wm = warp >> 2, wn = warp & 3;
    const int g = lane >> 2, i2 = (lane & 3) * 2;
    float acc[2][2][4] = {};

    for (int kc = 0; kc < 8; kc++) {
        int k0 = kc * 64;
        __syncthreads();
#pragma unroll
        for (int it = 0; it < 2; it++) {
            int c = tid + it * 256, r = c >> 3, col = (c & 7) * 8;
            *(uint4*)(A1 + r * LDA + col) = *(const uint4*)(g_hs + (size_t)(m0 + r) * Hz + k0 + col);
            *(uint4*)(B1 + r * LDB + col) = *(const uint4*)(g_Wo + (size_t)r * Hz + k0 + col);
        }
        __syncthreads();
#pragma unroll
        for (int kk = 0; kk < 4; kk++) {
            int k = kk * 16;
            unsigned a1f[2][4], b1f[2][2];
#pragma unroll
            for (int mt = 0; mt < 2; mt++) {
                int rbase = (wm * 32 + mt * 16 + g) * LDA + k + i2;
                load_afrag(a1f[mt], A1, rbase);
            }
#pragma unroll
            for (int nt = 0; nt < 2; nt++) {
                int rb = (wn * 16 + nt * 8 + g) * LDB + k + i2;
                b1f[nt][0] = *(const unsigned*)(B1 + rb);
                b1f[nt][1] = *(const unsigned*)(B1 + rb + 8);
            }
#pragma unroll
            for (int mt = 0; mt < 2; mt++)
#pragma unroll
                for (int nt = 0; nt < 2; nt++)
                    mma16816(acc[mt][nt], a1f[mt], b1f[nt][0], b1f[nt][1]);
        }
    }
#pragma unroll
    for (int mt = 0; mt < 2; mt++)
#pragma unroll
        for (int rs = 0; rs < 2; rs++)
#pragma unroll
            for (int jj = 0; jj < 2; jj++) {
                int m = m0 + wm * 32 + mt * 16 + g + rs * 8;
                int b = m & (Bz - 1), tt = m >> 9;
                int ci = rs * 2 + jj;
#pragma unroll
                for (int nt = 0; nt < 2; nt++) {
                    int v = wn * 16 + nt * 8 + i2 + jj;
                    out[((size_t)b * Tz + tt) * Vz + v] = acc[mt][nt][ci] + bout[v];
                }
            }
}

// ---------------- launch ----------------
extern "C" void kernel_launch(void* const* d_in, const int* in_sizes, int n_in,
                              void* d_out, int out_size) {
    const int* x   = (const int*)d_in[0];
    const int* tgt = (const int*)d_in[1];
    const float* eps   = (const float*)d_in[2];
    const float* emb   = (const float*)d_in[3];
    const float* Wih_f = (const float*)d_in[4];
    const float* Whh_f = (const float*)d_in[5];
    const float* b_f   = (const float*)d_in[6];
    const float* Wih_b = (const float*)d_in[7];
    const float* Whh_b = (const float*)d_in[8];
    const float* b_b   = (const float*)d_in[9];
    const float* W_mu  = (const float*)d_in[10];
    const float* b_mu  = (const float*)d_in[11];
    const float* W_lv  = (const float*)d_in[12];
    const float* b_lv  = (const float*)d_in[13];
    const float* W_di  = (const float*)d_in[14];
    const float* b_di  = (const float*)d_in[15];
    const float* Wih_d = (const float*)d_in[16];
    const float* Whh_d = (const float*)d_in[17];
    const float* b_d   = (const float*)d_in[18];
    const float* W_out = (const float*)d_in[19];
    const float* b_out = (const float*)d_in[20];

    float* out  = (float*)d_out;
    float* mu_o = out + (size_t)Bz * Tz * Vz;
    float* lv_o = mu_o + Bz * Lz;

    cudaFuncSetAttribute(k_steph,    cudaFuncAttributeMaxDynamicSharedMemorySize, SMEM_S);
    cudaFuncSetAttribute(k_outheadh, cudaFuncAttributeMaxDynamicSharedMemorySize, SMEM_OUT);

    __half *uf, *ub, *ud;
    float *ef, *eb, *ed, *hcat, *z, *zp, *htmp;
    cudaGetSymbolAddress((void**)&uf, g_Uf);
    cudaGetSymbolAddress((void**)&ub, g_Ub);
    cudaGetSymbolAddress((void**)&ud, g_Ud);
    cudaGetSymbolAddress((void**)&ef, g_EF);
    cudaGetSymbolAddress((void**)&eb, g_EB);
    cudaGetSymbolAddress((void**)&ed, g_ED);
    cudaGetSymbolAddress((void**)&hcat, g_hcat);
    cudaGetSymbolAddress((void**)&z, g_z);
    cudaGetSymbolAddress((void**)&zp, g_zp);
    cudaGetSymbolAddress((void**)&htmp, g_htmp);

    dim3 encGrid(Hz / 32, 16);   // 256 CTAs -> 2 CTAs/SM
    dim3 decGrid(Hz / 32, 8);    // 128 CTAs
    int zeroBlocks2 = (2 * Bz * Hz + 255) / 256;
    int zeroBlocks1 = (Bz * Hz + 255) / 256;

    // ---- fused prologue ----
    k_cvt_all<<<1024, 256>>>(Whh_f, Whh_b, Whh_d, W_out);
    k_tables<<<dim3(32, 3), 256>>>(emb, Wih_f, b_f, Wih_b, b_b, Wih_d, b_d);
    k_zero_state<<<zeroBlocks2, 256>>>();

    // ---- encoder (both directions, BM=64, 2 CTAs/SM) ----
    for (int t = 0; t < Tz; t++)
        k_steph<<<encGrid, 512, SMEM_S>>>(t, t & 1, 3, uf, ub, x, ef, eb, 0, 0);
    k_copy_hcat<<<zeroBlocks2, 256>>>();

    // ---- latent heads + reparameterize ----
    k_gemm<<<dim3(Lz / 64, Bz / 64), 256>>>(2 * Hz, hcat, 2 * Hz, W_mu, 2 * Hz, b_mu, mu_o, Lz);
    k_gemm<<<dim3(Lz / 64, Bz / 64), 256>>>(2 * Hz, hcat, 2 * Hz, W_lv, 2 * Hz, b_lv, lv_o, Lz);
    k_reparam<<<(Bz * Lz + 255) / 256, 256>>>(eps, mu_o, lv_o);

    // ---- decoder prologue ----
    k_gemm<<<dim3(G4z / 64, Bz / 64), 256>>>(Lz, z, Lz, Wih_d + Ez, ELz, nullptr, zp, G4z);
    k_gemm<<<dim3(Hz / 64, Bz / 64), 256>>>(Lz, z, Lz, W_di, Lz, b_di, htmp, Hz);
    k_hd_init<<<zeroBlocks1, 256>>>();

    // ---- decoder recurrence ----
    for (int t = 0; t < Tz; t++)
        k_steph<<<decGrid, 512, SMEM_S>>>(t, t & 1, 3, ud, ud, tgt, ed, ed, 1, 1);

    // ---- output head ----
    k_outheadh<<<(Tz * Bz) / 64, 256, SMEM_OUT>>>(b_out, out);
}

// round 15
// speedup vs baseline: 1.1646x; 1.1646x over previous
#include <cuda_runtime.h>
#include <cuda_fp16.h>
#include <math.h>

#define Bz 512
#define Tz 128
#define Vz 64
#define Ez 256
#define Hz 512
#define Lz 128
#define G4z 2048
#define ELz 384
#define LDA 72
#define LDB 72
#define LDK 136   // row stride (halves) for 128-col step tiles; conflict-free

// ---------------- scratch ----------------
__device__ __align__(16) __half g_h[2][2 * Bz * Hz];
__device__ __align__(16) float  g_c[2 * Bz * Hz];
__device__ __align__(16) float  g_htmp[Bz * Hz];
__device__ __align__(16) float  g_hcat[Bz * 2 * Hz];
__device__ __align__(16) float  g_z[Bz * Lz];
__device__ __align__(16) float  g_zp[Bz * G4z];
__device__ __align__(16) __half g_hs[(size_t)Tz * Bz * Hz];
__device__ __align__(16) float  g_EF[Vz * G4z];
__device__ __align__(16) float  g_EB[Vz * G4z];
__device__ __align__(16) float  g_ED[Vz * G4z];
__device__ __align__(16) __half g_Uf[G4z * Hz];
__device__ __align__(16) __half g_Ub[G4z * Hz];
__device__ __align__(16) __half g_Ud[G4z * Hz];
__device__ __align__(16) __half g_Wo[Vz * Hz];

__device__ __forceinline__ float sigm(float x) { return 1.0f / (1.0f + expf(-x)); }

__device__ __forceinline__ void mma16816(float* d, const unsigned* a, unsigned b0, unsigned b1) {
    asm volatile("mma.sync.aligned.m16n8k16.row.col.f32.f16.f16.f32 "
                 "{%0,%1,%2,%3},{%4,%5,%6,%7},{%8,%9},{%0,%1,%2,%3};"
                 : "+f"(d[0]), "+f"(d[1]), "+f"(d[2]), "+f"(d[3])
                 : "r"(a[0]), "r"(a[1]), "r"(a[2]), "r"(a[3]), "r"(b0), "r"(b1));
}
__device__ __forceinline__ unsigned su(const void* p) {
    return (unsigned)__cvta_generic_to_shared(p);
}
__device__ __forceinline__ void cpa16(void* dst, const void* src) {
    asm volatile("cp.async.cg.shared.global [%0], [%1], 16;" :: "r"(su(dst)), "l"(src));
}
#define CP_COMMIT() asm volatile("cp.async.commit_group;")
#define CP_WAIT0()  asm volatile("cp.async.wait_group 0;")

__device__ __forceinline__ void ldm_x4(unsigned& r0, unsigned& r1, unsigned& r2, unsigned& r3,
                                       const void* p) {
    asm volatile("ldmatrix.sync.aligned.m8n8.x4.shared.b16 {%0,%1,%2,%3}, [%4];"
                 : "=r"(r0), "=r"(r1), "=r"(r2), "=r"(r3) : "r"(su(p)));
}

// encoder: 2 stages x {A: 128xLDK, B: 128xLDK}
#define SMEM_E (2 * (256 * LDK) * 2)    // 139264 B
// decoder: 2 stages x {A: 64xLDK, B: 128xLDK}
#define SMEM_D (2 * (192 * LDK) * 2)    // 104448 B
#define SMEM_OUT ((64*LDA + 64*LDB) * 2)
extern __shared__ __half smh[];

__device__ __forceinline__ void load_afrag(unsigned* f, const __half* A, int rbase) {
    f[0] = *(const unsigned*)(A + rbase);
    f[1] = *(const unsigned*)(A + rbase + 8 * LDA);
    f[2] = *(const unsigned*)(A + rbase + 8);
    f[3] = *(const unsigned*)(A + rbase + 8 * LDA + 8);
}

// ---------------- fused prologue kernels ----------------
__global__ void k_cvt_all(const float* __restrict__ wf, const float* __restrict__ wb,
                          const float* __restrict__ wd, const float* __restrict__ wo) {
    const int NU = G4z * Hz;
    const int NT = 3 * NU + Vz * Hz;
    int i = blockIdx.x * blockDim.x + threadIdx.x;
    for (; i < NT; i += gridDim.x * blockDim.x) {
        if (i < NU)               g_Uf[i] = __float2half_rn(wf[i]);
        else if (i < 2 * NU)      g_Ub[i - NU] = __float2half_rn(wb[i - NU]);
        else if (i < 3 * NU)      g_Ud[i - 2 * NU] = __float2half_rn(wd[i - 2 * NU]);
        else                      g_Wo[i - 3 * NU] = __float2half_rn(wo[i - 3 * NU]);
    }
}
__global__ void k_zero_state() {
    int i = blockIdx.x * blockDim.x + threadIdx.x;
    if (i < 2 * Bz * Hz) {
        __half zz = __float2half(0.f);
        g_h[0][i] = zz; g_h[1][i] = zz; g_c[i] = 0.f;
    }
}
__global__ void k_hd_init() {
    int i = blockIdx.x * blockDim.x + threadIdx.x;
    if (i < Bz * Hz) { g_h[0][i] = __float2half_rn(g_htmp[i]); g_c[i] = 0.f; }
}
__global__ void k_copy_hcat() {
    int i = blockIdx.x * blockDim.x + threadIdx.x;
    if (i < 2 * Bz * Hz) {
        int s = i >> 9;
        int j = i & (Hz - 1);
        int b = s & (Bz - 1);
        int dir = s >> 9;
        g_hcat[b * (2 * Hz) + dir * Hz + j] = __half2float(g_h[0][i]);
    }
}
__global__ void k_reparam(const float* __restrict__ eps, const float* __restrict__ muv,
                          const float* __restrict__ lvv) {
    int i = blockIdx.x * blockDim.x + threadIdx.x;
    if (i < Bz * Lz) g_z[i] = muv[i] + eps[i] * expf(0.5f * lvv[i]);
}

// ---------------- fp32 GEMM body (shared) ----------------
__device__ __forceinline__ void gemm_body(int K,
                                          const float* __restrict__ A, int lda,
                                          const float* __restrict__ Bw, int ldb,
                                          const float* __restrict__ bias,
                                          float* __restrict__ C, int ldc,
                                          int m0, int n0) {
    __shared__ float As[16][68];
    __shared__ float Bs[16][68];
    const int tid = threadIdx.x;
    const int lr = tid >> 2, lk = tid & 3;
    const int tx = tid & 15, ty = tid >> 4;
    float acc[4][4] = {};
    for (int k0 = 0; k0 < K; k0 += 16) {
        float4 av = *(const float4*)(A + (size_t)(m0 + lr) * lda + k0 + lk * 4);
        float4 bv = *(const float4*)(Bw + (size_t)(n0 + lr) * ldb + k0 + lk * 4);
        __syncthreads();
        As[lk*4+0][lr]=av.x; As[lk*4+1][lr]=av.y; As[lk*4+2][lr]=av.z; As[lk*4+3][lr]=av.w;
        Bs[lk*4+0][lr]=bv.x; Bs[lk*4+1][lr]=bv.y; Bs[lk*4+2][lr]=bv.z; Bs[lk*4+3][lr]=bv.w;
        __syncthreads();
#pragma unroll
        for (int k = 0; k < 16; k++) {
            float4 a = *(const float4*)&As[k][ty*4];
            float4 b = *(const float4*)&Bs[k][tx*4];
            acc[0][0]+=a.x*b.x; acc[0][1]+=a.x*b.y; acc[0][2]+=a.x*b.z; acc[0][3]+=a.x*b.w;
            acc[1][0]+=a.y*b.x; acc[1][1]+=a.y*b.y; acc[1][2]+=a.y*b.z; acc[1][3]+=a.y*b.w;
            acc[2][0]+=a.z*b.x; acc[2][1]+=a.z*b.y; acc[2][2]+=a.z*b.z; acc[2][3]+=a.z*b.w;
            acc[3][0]+=a.w*b.x; acc[3][1]+=a.w*b.y; acc[3][2]+=a.w*b.z; acc[3][3]+=a.w*b.w;
        }
    }
#pragma unroll
    for (int i = 0; i < 4; i++)
#pragma unroll
        for (int j = 0; j < 4; j++) {
            int n = n0 + tx * 4 + j;
            float bb = bias ? bias[n] : 0.0f;
            C[(size_t)(m0 + ty * 4 + i) * ldc + n] = acc[i][j] + bb;
        }
}
__global__ __launch_bounds__(256) void k_gemm(int K,
                                              const float* __restrict__ A, int lda,
                                              const float* __restrict__ Bw, int ldb,
                                              const float* __restrict__ bias,
                                              float* __restrict__ C, int ldc) {
    gemm_body(K, A, lda, Bw, ldb, bias, C, ldc, blockIdx.y * 64, blockIdx.x * 64);
}
__global__ __launch_bounds__(256) void k_tables(const float* __restrict__ emb,
                                                const float* __restrict__ Wf,
                                                const float* __restrict__ bf,
                                                const float* __restrict__ Wb,
                                                const float* __restrict__ bb,
                                                const float* __restrict__ Wd,
                                                const float* __restrict__ bd) {
    int tbl = blockIdx.y;
    const float* W = (tbl == 0) ? Wf : (tbl == 1) ? Wb : Wd;
    const float* bi = (tbl == 0) ? bf : (tbl == 1) ? bb : bd;
    float* C = (tbl == 0) ? g_EF : (tbl == 1) ? g_EB : g_ED;
    int ldb = (tbl == 2) ? ELz : Ez;
    gemm_body(Ez, emb, Ez, W, ldb, bi, C, G4z, 0, blockIdx.x * 64);
}

// =============================================================================
// Step kernels (R13 geometry) with ldmatrix fragment loads.
// 512 threads, 16 warps 4m x 4n, warp tile 32x32 (enc) / 16x32 (dec).
// K-chunk 128, 2-stage cp.async.
// =============================================================================

// ---------------- decoder step: BM=64 ----------------
__global__ __launch_bounds__(512) void k_steph(int t, int pin,
                                               const __half* __restrict__ U1,
                                               const int* __restrict__ ids,
                                               const float* __restrict__ E,
                                               int use_zp, int store_hs) {
    __shared__ int toks[64];
    const int tid = threadIdx.x;
    const int b0 = blockIdx.y * 64;
    const int j0 = blockIdx.x * 32;
    const __half* h1 = g_h[pin];
    const int lane = tid & 31, warp = tid >> 5;
    const int wm = warp >> 2, wn = warp & 3;
    const int g = lane >> 2, i2 = (lane & 3) * 2;
    // ldmatrix per-lane address components
    const int lmA_row = lane & 15, lmA_koff = (lane >> 4) * 8;
    const int lmB_rowl = (lane >> 4) * 8 + (lane & 7);       // within a 2-tile group
    const int lmB_koff = ((lane >> 3) & 1) * 8;

    if (tid < 64) toks[tid] = ids[(b0 + tid) * Tz + t];

    __half* Abase = smh;                 // [stage][64][LDK]
    __half* Bbase = smh + 2 * 64 * LDK;  // [stage][128][LDK]
#define A_ST(st) (Abase + (st) * 64 * LDK)
#define B_ST(st) (Bbase + (st) * 128 * LDK)

    auto stage_load = [&](int st, int k0) {
#pragma unroll
        for (int it = 0; it < 2; it++) {
            int c = tid + it * 512, r = c >> 4, kc8 = c & 15;
            cpa16(A_ST(st) + r * LDK + kc8 * 8, h1 + (size_t)(b0 + r) * Hz + k0 + kc8 * 8);
        }
#pragma unroll
        for (int it = 0; it < 4; it++) {
            int c = tid + it * 512, r = c >> 4, kc8 = c & 15;
            int q = (r >> 3) & 3, wnr = r >> 5, s = r & 7;
            size_t goff = (size_t)(q * Hz + j0 + wnr * 8 + s) * Hz + k0 + kc8 * 8;
            cpa16(B_ST(st) + r * LDK + kc8 * 8, U1 + goff);
        }
    };

    float acc[4][4] = {};
    stage_load(0, 0);
    CP_COMMIT();

    for (int kc = 0; kc < 4; kc++) {
        CP_WAIT0();
        __syncthreads();
        if (kc < 3) {
            stage_load((kc + 1) & 1, (kc + 1) * 128);
            CP_COMMIT();
        }
        const __half* A1 = A_ST(kc & 1);
        const __half* B1 = B_ST(kc & 1);
#pragma unroll
        for (int kk = 0; kk < 8; kk++) {
            int k = kk * 16;
            unsigned a1f[4], b1f[4][2];
            ldm_x4(a1f[0], a1f[1], a1f[2], a1f[3],
                   A1 + (wm * 16 + lmA_row) * LDK + k + lmA_koff);
#pragma unroll
            for (int q2 = 0; q2 < 2; q2++)
                ldm_x4(b1f[q2*2][0], b1f[q2*2][1], b1f[q2*2+1][0], b1f[q2*2+1][1],
                       B1 + (wn * 32 + q2 * 16 + lmB_rowl) * LDK + k + lmB_koff);
#pragma unroll
            for (int q = 0; q < 4; q++)
                mma16816(acc[q], a1f, b1f[q][0], b1f[q][1]);
        }
    }

    __half* o1 = g_h[pin ^ 1];
    const int jb = j0 + wn * 8 + i2;
#pragma unroll
    for (int rs = 0; rs < 2; rs++) {
        int r = wm * 16 + g + rs * 8;
        int b = b0 + r;
        int tok = toks[r];
        float2 gv[4];
#pragma unroll
        for (int q = 0; q < 4; q++) {
            int n = q * Hz + jb;
            float2 e = *(const float2*)&E[(size_t)tok * G4z + n];
            if (use_zp) {
                float2 zp2 = *(const float2*)&g_zp[(size_t)b * G4z + n];
                e.x += zp2.x; e.y += zp2.y;
            }
            gv[q] = make_float2(acc[q][rs * 2 + 0] + e.x, acc[q][rs * 2 + 1] + e.y);
        }
        int idx = b * Hz + jb;
        float2 cold = *(const float2*)&g_c[idx];
        float cn0 = sigm(gv[1].x) * cold.x + sigm(gv[0].x) * tanhf(gv[2].x);
        float cn1 = sigm(gv[1].y) * cold.y + sigm(gv[0].y) * tanhf(gv[2].y);
        float hn0 = sigm(gv[3].x) * tanhf(cn0);
        float hn1 = sigm(gv[3].y) * tanhf(cn1);
        *(float2*)&g_c[idx] = make_float2(cn0, cn1);
        __half2 hp = __halves2half2(__float2half_rn(hn0), __float2half_rn(hn1));
        *(__half2*)&o1[idx] = hp;
        if (store_hs)
            *(__half2*)&g_hs[((size_t)t * Bz + b) * Hz + jb] = hp;
    }
#undef A_ST
#undef B_ST
}

// ---------------- encoder step: BM=128 (both dirs), 1 wave ----------------
__global__ __launch_bounds__(512) void k_steph2(int t, int pin,
                                                const __half* __restrict__ U1a,
                                                const __half* __restrict__ U1b,
                                                const int* __restrict__ ids,
                                                const float* __restrict__ Ea,
                                                const float* __restrict__ Eb) {
    __shared__ int toks[128];
    const int tid = threadIdx.x;
    const int by = blockIdx.y;
    const int dir = by >> 2;
    const int b0 = (by & 3) * 128;
    const int sb0 = dir * Bz + b0;
    const int j0 = blockIdx.x * 32;
    const __half* U1 = dir ? U1b : U1a;
    const float*  E  = dir ? Eb  : Ea;
    const __half* h1 = g_h[pin];
    const int lane = tid & 31, warp = tid >> 5;
    const int wm = warp >> 2, wn = warp & 3;
    const int g = lane >> 2, i2 = (lane & 3) * 2;
    const int lmA_row = lane & 15, lmA_koff = (lane >> 4) * 8;
    const int lmB_rowl = (lane >> 4) * 8 + (lane & 7);
    const int lmB_koff = ((lane >> 3) & 1) * 8;

    if (tid < 128) {
        int tt = dir ? (Tz - 1 - t) : t;
        toks[tid] = ids[(b0 + tid) * Tz + tt];
    }

    __half* Abase = smh;                  // [stage][128][LDK]
    __half* Bbase = smh + 2 * 128 * LDK;  // [stage][128][LDK]
#define A2_ST(st) (Abase + (st) * 128 * LDK)
#define B2_ST(st) (Bbase + (st) * 128 * LDK)

    auto stage_load = [&](int st, int k0) {
#pragma unroll
        for (int it = 0; it < 4; it++) {
            int c = tid + it * 512, r = c >> 4, kc8 = c & 15;
            cpa16(A2_ST(st) + r * LDK + kc8 * 8, h1 + (size_t)(sb0 + r) * Hz + k0 + kc8 * 8);
        }
#pragma unroll
        for (int it = 0; it < 4; it++) {
            int c = tid + it * 512, r = c >> 4, kc8 = c & 15;
            int q = (r >> 3) & 3, wnr = r >> 5, s = r & 7;
            size_t goff = (size_t)(q * Hz + j0 + wnr * 8 + s) * Hz + k0 + kc8 * 8;
            cpa16(B2_ST(st) + r * LDK + kc8 * 8, U1 + goff);
        }
    };

    float acc[2][4][4] = {};
    stage_load(0, 0);
    CP_COMMIT();

    for (int kc = 0; kc < 4; kc++) {
        CP_WAIT0();
        __syncthreads();
        if (kc < 3) {
            stage_load((kc + 1) & 1, (kc + 1) * 128);
            CP_COMMIT();
        }
        const __half* A1 = A2_ST(kc & 1);
        const __half* B1 = B2_ST(kc & 1);
#pragma unroll
        for (int kk = 0; kk < 8; kk++) {
            int k = kk * 16;
            unsigned a1f[2][4], b1f[4][2];
#pragma unroll
            for (int mt = 0; mt < 2; mt++)
                ldm_x4(a1f[mt][0], a1f[mt][1], a1f[mt][2], a1f[mt][3],
                       A1 + (wm * 32 + mt * 16 + lmA_row) * LDK + k + lmA_koff);
#pragma unroll
            for (int q2 = 0; q2 < 2; q2++)
                ldm_x4(b1f[q2*2][0], b1f[q2*2][1], b1f[q2*2+1][0], b1f[q2*2+1][1],
                       B1 + (wn * 32 + q2 * 16 + lmB_rowl) * LDK + k + lmB_koff);
#pragma unroll
            for (int mt = 0; mt < 2; mt++)
#pragma unroll
                for (int q = 0; q < 4; q++)
                    mma16816(acc[mt][q], a1f[mt], b1f[q][0], b1f[q][1]);
        }
    }

    __half* o1 = g_h[pin ^ 1];
    const int jb = j0 + wn * 8 + i2;
#pragma unroll
    for (int mt = 0; mt < 2; mt++)
#pragma unroll
        for (int rs = 0; rs < 2; rs++) {
            int r = wm * 32 + mt * 16 + g + rs * 8;
            int sb = sb0 + r;
            int tok = toks[r];
            float2 gv[4];
#pragma unroll
            for (int q = 0; q < 4; q++) {
                float2 e = *(const float2*)&E[(size_t)tok * G4z + q * Hz + jb];
                gv[q] = make_float2(acc[mt][q][rs * 2 + 0] + e.x,
                                    acc[mt][q][rs * 2 + 1] + e.y);
            }
            int idx = sb * Hz + jb;
            float2 cold = *(const float2*)&g_c[idx];
            float cn0 = sigm(gv[1].x) * cold.x + sigm(gv[0].x) * tanhf(gv[2].x);
            float cn1 = sigm(gv[1].y) * cold.y + sigm(gv[0].y) * tanhf(gv[2].y);
            float hn0 = sigm(gv[3].x) * tanhf(cn0);
            float hn1 = sigm(gv[3].y) * tanhf(cn1);
            *(float2*)&g_c[idx] = make_float2(cn0, cn1);
            *(__half2*)&o1[idx] =
                __halves2half2(__float2half_rn(hn0), __float2half_rn(hn1));
        }
#undef A2_ST
#undef B2_ST
}

// ---------------- output head: 1-MMA mma.sync (R10-proven) ----------------
__global__ __launch_bounds__(256) void k_outheadh(const float* __restrict__ bout,
                                                  float* __restrict__ out) {
    __half* A1 = smh;
    __half* B1 = smh + 64 * LDA;
    const int tid = threadIdx.x;
    const int m0 = blockIdx.x * 64;
    const int lane = tid & 31, warp = tid >> 5;
    const int wm = warp >> 2, wn = warp & 3;
    const int g = lane >> 2, i2 = (lane & 3) * 2;
    float acc[2][2][4] = {};

    for (int kc = 0; kc < 8; kc++) {
        int k0 = kc * 64;
        __syncthreads();
#pragma unroll
        for (int it = 0; it < 2; it++) {
            int c = tid + it * 256, r = c >> 3, col = (c & 7) * 8;
            *(uint4*)(A1 + r * LDA + col) = *(const uint4*)(g_hs + (size_t)(m0 + r) * Hz + k0 + col);
            *(uint4*)(B1 + r * LDB + col) = *(const uint4*)(g_Wo + (size_t)r * Hz + k0 + col);
        }
        __syncthreads();
#pragma unroll
        for (int kk = 0; kk < 4; kk++) {
            int k = kk * 16;
            unsigned a1f[2][4], b1f[2][2];
#pragma unroll
            for (int mt = 0; mt < 2; mt++) {
                int rbase = (wm * 32 + mt * 16 + g) * LDA + k + i2;
                load_afrag(a1f[mt], A1, rbase);
            }
#pragma unroll
            for (int nt = 0; nt < 2; nt++) {
                int rb = (wn * 16 + nt * 8 + g) * LDB + k + i2;
                b1f[nt][0] = *(const unsigned*)(B1 + rb);
                b1f[nt][1] = *(const unsigned*)(B1 + rb + 8);
            }
#pragma unroll
            for (int mt = 0; mt < 2; mt++)
#pragma unroll
                for (int nt = 0; nt < 2; nt++)
                    mma16816(acc[mt][nt], a1f[mt], b1f[nt][0], b1f[nt][1]);
        }
    }
#pragma unroll
    for (int mt = 0; mt < 2; mt++)
#pragma unroll
        for (int rs = 0; rs < 2; rs++)
#pragma unroll
            for (int jj = 0; jj < 2; jj++) {
                int m = m0 + wm * 32 + mt * 16 + g + rs * 8;
                int b = m & (Bz - 1), tt = m >> 9;
                int ci = rs * 2 + jj;
#pragma unroll
                for (int nt = 0; nt < 2; nt++) {
                    int v = wn * 16 + nt * 8 + i2 + jj;
                    out[((size_t)b * Tz + tt) * Vz + v] = acc[mt][nt][ci] + bout[v];
                }
            }
}

// ---------------- launch ----------------
extern "C" void kernel_launch(void* const* d_in, const int* in_sizes, int n_in,
                              void* d_out, int out_size) {
    const int* x   = (const int*)d_in[0];
    const int* tgt = (const int*)d_in[1];
    const float* eps   = (const float*)d_in[2];
    const float* emb   = (const float*)d_in[3];
    const float* Wih_f = (const float*)d_in[4];
    const float* Whh_f = (const float*)d_in[5];
    const float* b_f   = (const float*)d_in[6];
    const float* Wih_b = (const float*)d_in[7];
    const float* Whh_b = (const float*)d_in[8];
    const float* b_b   = (const float*)d_in[9];
    const float* W_mu  = (const float*)d_in[10];
    const float* b_mu  = (const float*)d_in[11];
    const float* W_lv  = (const float*)d_in[12];
    const float* b_lv  = (const float*)d_in[13];
    const float* W_di  = (const float*)d_in[14];
    const float* b_di  = (const float*)d_in[15];
    const float* Wih_d = (const float*)d_in[16];
    const float* Whh_d = (const float*)d_in[17];
    const float* b_d   = (const float*)d_in[18];
    const float* W_out = (const float*)d_in[19];
    const float* b_out = (const float*)d_in[20];

    float* out  = (float*)d_out;
    float* mu_o = out + (size_t)Bz * Tz * Vz;
    float* lv_o = mu_o + Bz * Lz;

    cudaFuncSetAttribute(k_steph,    cudaFuncAttributeMaxDynamicSharedMemorySize, SMEM_D);
    cudaFuncSetAttribute(k_steph2,   cudaFuncAttributeMaxDynamicSharedMemorySize, SMEM_E);
    cudaFuncSetAttribute(k_outheadh, cudaFuncAttributeMaxDynamicSharedMemorySize, SMEM_OUT);

    __half *uf, *ub, *ud;
    float *ef, *eb, *ed, *hcat, *z, *zp, *htmp;
    cudaGetSymbolAddress((void**)&uf, g_Uf);
    cudaGetSymbolAddress((void**)&ub, g_Ub);
    cudaGetSymbolAddress((void**)&ud, g_Ud);
    cudaGetSymbolAddress((void**)&ef, g_EF);
    cudaGetSymbolAddress((void**)&eb, g_EB);
    cudaGetSymbolAddress((void**)&ed, g_ED);
    cudaGetSymbolAddress((void**)&hcat, g_hcat);
    cudaGetSymbolAddress((void**)&z, g_z);
    cudaGetSymbolAddress((void**)&zp, g_zp);
    cudaGetSymbolAddress((void**)&htmp, g_htmp);

    dim3 encGrid(Hz / 32, 8);    // 128 CTAs, both dirs, 1 wave
    dim3 decGrid(Hz / 32, 8);    // 128 CTAs
    int zeroBlocks2 = (2 * Bz * Hz + 255) / 256;
    int zeroBlocks1 = (Bz * Hz + 255) / 256;

    // ---- fused prologue ----
    k_cvt_all<<<1024, 256>>>(Whh_f, Whh_b, Whh_d, W_out);
    k_tables<<<dim3(32, 3), 256>>>(emb, Wih_f, b_f, Wih_b, b_b, Wih_d, b_d);
    k_zero_state<<<zeroBlocks2, 256>>>();

    // ---- encoder (both directions, BM=128) ----
    for (int t = 0; t < Tz; t++)
        k_steph2<<<encGrid, 512, SMEM_E>>>(t, t & 1, uf, ub, x, ef, eb);
    k_copy_hcat<<<zeroBlocks2, 256>>>();

    // ---- latent heads + reparameterize ----
    k_gemm<<<dim3(Lz / 64, Bz / 64), 256>>>(2 * Hz, hcat, 2 * Hz, W_mu, 2 * Hz, b_mu, mu_o, Lz);
    k_gemm<<<dim3(Lz / 64, Bz / 64), 256>>>(2 * Hz, hcat, 2 * Hz, W_lv, 2 * Hz, b_lv, lv_o, Lz);
    k_reparam<<<(Bz * Lz + 255) / 256, 256>>>(eps, mu_o, lv_o);

    // ---- decoder prologue ----
    k_gemm<<<dim3(G4z / 64, Bz / 64), 256>>>(Lz, z, Lz, Wih_d + Ez, ELz, nullptr, zp, G4z);
    k_gemm<<<dim3(Hz / 64, Bz / 64), 256>>>(Lz, z, Lz, W_di, Lz, b_di, htmp, Hz);
    k_hd_init<<<zeroBlocks1, 256>>>();

    // ---- decoder recurrence ----
    for (int t = 0; t < Tz; t++)
        k_steph<<<decGrid, 512, SMEM_D>>>(t, t & 1, ud, tgt, ed, 1, 1);

    // ---- output head ----
    k_outheadh<<<(Tz * Bz) / 64, 256, SMEM_OUT>>>(b_out, out);
}

// round 16
// speedup vs baseline: 1.1686x; 1.0035x over previous
#include <cuda_runtime.h>
#include <cuda_fp16.h>
#include <math.h>

#define Bz 512
#define Tz 128
#define Vz 64
#define Ez 256
#define Hz 512
#define Lz 128
#define G4z 2048
#define ELz 384
#define LDA 72
#define LDB 72
#define LDK 136

// ---------------- scratch ----------------
__device__ __align__(16) __half g_h[2][2 * Bz * Hz];
__device__ __align__(16) float  g_c[2 * Bz * Hz];
__device__ __align__(16) float  g_htmp[Bz * Hz];
__device__ __align__(16) float  g_hcat[Bz * 2 * Hz];
__device__ __align__(16) float  g_z[Bz * Lz];
__device__ __align__(16) float  g_zp[Bz * G4z];
__device__ __align__(16) __half g_hs[(size_t)Tz * Bz * Hz];
__device__ __align__(16) float  g_EF[Vz * G4z];
__device__ __align__(16) float  g_EB[Vz * G4z];
__device__ __align__(16) float  g_ED[Vz * G4z];
__device__ __align__(16) __half g_Uf[G4z * Hz];
__device__ __align__(16) __half g_Ub[G4z * Hz];
__device__ __align__(16) __half g_Ud[G4z * Hz];
__device__ __align__(16) __half g_Wo[Vz * Hz];

__device__ __forceinline__ float sigm(float x) { return 1.0f / (1.0f + expf(-x)); }

__device__ __forceinline__ void mma16816(float* d, const unsigned* a, unsigned b0, unsigned b1) {
    asm volatile("mma.sync.aligned.m16n8k16.row.col.f32.f16.f16.f32 "
                 "{%0,%1,%2,%3},{%4,%5,%6,%7},{%8,%9},{%0,%1,%2,%3};"
                 : "+f"(d[0]), "+f"(d[1]), "+f"(d[2]), "+f"(d[3])
                 : "r"(a[0]), "r"(a[1]), "r"(a[2]), "r"(a[3]), "r"(b0), "r"(b1));
}
__device__ __forceinline__ unsigned su(const void* p) {
    return (unsigned)__cvta_generic_to_shared(p);
}
__device__ __forceinline__ void cpa16(void* dst, const void* src) {
    asm volatile("cp.async.cg.shared.global [%0], [%1], 16;" :: "r"(su(dst)), "l"(src));
}
#define CP_COMMIT() asm volatile("cp.async.commit_group;")
#define CP_WAIT1()  asm volatile("cp.async.wait_group 1;")
#define CP_WAIT0()  asm volatile("cp.async.wait_group 0;")

__device__ __forceinline__ void ldm_x4(unsigned& r0, unsigned& r1, unsigned& r2, unsigned& r3,
                                       const void* p) {
    asm volatile("ldmatrix.sync.aligned.m8n8.x4.shared.b16 {%0,%1,%2,%3}, [%4];"
                 : "=r"(r0), "=r"(r1), "=r"(r2), "=r"(r3) : "r"(su(p)));
}

// encoder: 3 stages x {A: 128xLDK, B: 128xLDK} = 208896 B
#define SMEM_E (3 * (256 * LDK) * 2)
// decoder: 3 stages x {A: 64xLDK, B: 128xLDK} = 156672 B
#define SMEM_D (3 * (192 * LDK) * 2)
#define SMEM_OUT ((64*LDA + 64*LDB) * 2)
extern __shared__ __half smh[];

__device__ __forceinline__ void load_afrag(unsigned* f, const __half* A, int rbase) {
    f[0] = *(const unsigned*)(A + rbase);
    f[1] = *(const unsigned*)(A + rbase + 8 * LDA);
    f[2] = *(const unsigned*)(A + rbase + 8);
    f[3] = *(const unsigned*)(A + rbase + 8 * LDA + 8);
}

// ---------------- fused prologue kernels ----------------
__global__ void k_cvt_all(const float* __restrict__ wf, const float* __restrict__ wb,
                          const float* __restrict__ wd, const float* __restrict__ wo) {
    const int NU = G4z * Hz;
    const int NT = 3 * NU + Vz * Hz;
    int i = blockIdx.x * blockDim.x + threadIdx.x;
    for (; i < NT; i += gridDim.x * blockDim.x) {
        if (i < NU)               g_Uf[i] = __float2half_rn(wf[i]);
        else if (i < 2 * NU)      g_Ub[i - NU] = __float2half_rn(wb[i - NU]);
        else if (i < 3 * NU)      g_Ud[i - 2 * NU] = __float2half_rn(wd[i - 2 * NU]);
        else                      g_Wo[i - 3 * NU] = __float2half_rn(wo[i - 3 * NU]);
    }
}
__global__ void k_zero_state() {
    int i = blockIdx.x * blockDim.x + threadIdx.x;
    if (i < 2 * Bz * Hz) {
        __half zz = __float2half(0.f);
        g_h[0][i] = zz; g_h[1][i] = zz; g_c[i] = 0.f;
    }
}
__global__ void k_hd_init() {
    int i = blockIdx.x * blockDim.x + threadIdx.x;
    if (i < Bz * Hz) { g_h[0][i] = __float2half_rn(g_htmp[i]); g_c[i] = 0.f; }
}
__global__ void k_copy_hcat() {
    int i = blockIdx.x * blockDim.x + threadIdx.x;
    if (i < 2 * Bz * Hz) {
        int s = i >> 9;
        int j = i & (Hz - 1);
        int b = s & (Bz - 1);
        int dir = s >> 9;
        g_hcat[b * (2 * Hz) + dir * Hz + j] = __half2float(g_h[0][i]);
    }
}
__global__ void k_reparam(const float* __restrict__ eps, const float* __restrict__ muv,
                          const float* __restrict__ lvv) {
    int i = blockIdx.x * blockDim.x + threadIdx.x;
    if (i < Bz * Lz) g_z[i] = muv[i] + eps[i] * expf(0.5f * lvv[i]);
}

// ---------------- fp32 GEMM body ----------------
__device__ __forceinline__ void gemm_body(int K,
                                          const float* __restrict__ A, int lda,
                                          const float* __restrict__ Bw, int ldb,
                                          const float* __restrict__ bias,
                                          float* __restrict__ C, int ldc,
                                          int m0, int n0) {
    __shared__ float As[16][68];
    __shared__ float Bs[16][68];
    const int tid = threadIdx.x;
    const int lr = tid >> 2, lk = tid & 3;
    const int tx = tid & 15, ty = tid >> 4;
    float acc[4][4] = {};
    for (int k0 = 0; k0 < K; k0 += 16) {
        float4 av = *(const float4*)(A + (size_t)(m0 + lr) * lda + k0 + lk * 4);
        float4 bv = *(const float4*)(Bw + (size_t)(n0 + lr) * ldb + k0 + lk * 4);
        __syncthreads();
        As[lk*4+0][lr]=av.x; As[lk*4+1][lr]=av.y; As[lk*4+2][lr]=av.z; As[lk*4+3][lr]=av.w;
        Bs[lk*4+0][lr]=bv.x; Bs[lk*4+1][lr]=bv.y; Bs[lk*4+2][lr]=bv.z; Bs[lk*4+3][lr]=bv.w;
        __syncthreads();
#pragma unroll
        for (int k = 0; k < 16; k++) {
            float4 a = *(const float4*)&As[k][ty*4];
            float4 b = *(const float4*)&Bs[k][tx*4];
            acc[0][0]+=a.x*b.x; acc[0][1]+=a.x*b.y; acc[0][2]+=a.x*b.z; acc[0][3]+=a.x*b.w;
            acc[1][0]+=a.y*b.x; acc[1][1]+=a.y*b.y; acc[1][2]+=a.y*b.z; acc[1][3]+=a.y*b.w;
            acc[2][0]+=a.z*b.x; acc[2][1]+=a.z*b.y; acc[2][2]+=a.z*b.z; acc[2][3]+=a.z*b.w;
            acc[3][0]+=a.w*b.x; acc[3][1]+=a.w*b.y; acc[3][2]+=a.w*b.z; acc[3][3]+=a.w*b.w;
        }
    }
#pragma unroll
    for (int i = 0; i < 4; i++)
#pragma unroll
        for (int j = 0; j < 4; j++) {
            int n = n0 + tx * 4 + j;
            float bb = bias ? bias[n] : 0.0f;
            C[(size_t)(m0 + ty * 4 + i) * ldc + n] = acc[i][j] + bb;
        }
}
__global__ __launch_bounds__(256) void k_gemm(int K,
                                              const float* __restrict__ A, int lda,
                                              const float* __restrict__ Bw, int ldb,
                                              const float* __restrict__ bias,
                                              float* __restrict__ C, int ldc) {
    gemm_body(K, A, lda, Bw, ldb, bias, C, ldc, blockIdx.y * 64, blockIdx.x * 64);
}
__global__ __launch_bounds__(256) void k_tables(const float* __restrict__ emb,
                                                const float* __restrict__ Wf,
                                                const float* __restrict__ bf,
                                                const float* __restrict__ Wb,
                                                const float* __restrict__ bb,
                                                const float* __restrict__ Wd,
                                                const float* __restrict__ bd) {
    int tbl = blockIdx.y;
    const float* W = (tbl == 0) ? Wf : (tbl == 1) ? Wb : Wd;
    const float* bi = (tbl == 0) ? bf : (tbl == 1) ? bb : bd;
    float* C = (tbl == 0) ? g_EF : (tbl == 1) ? g_EB : g_ED;
    int ldb = (tbl == 2) ? ELz : Ez;
    gemm_body(Ez, emb, Ez, W, ldb, bi, C, G4z, 0, blockIdx.x * 64);
}

// =============================================================================
// Step kernels: ldmatrix frags, K-chunk 128, 3-stage cp.async (WAIT1),
// epilogue operands (tok -> E(+zp), c) prefetched into registers at entry.
// =============================================================================

// ---------------- decoder step: BM=64 ----------------
__global__ __launch_bounds__(512) void k_steph(int t, int pin,
                                               const __half* __restrict__ U1,
                                               const int* __restrict__ ids,
                                               const float* __restrict__ E,
                                               int use_zp, int store_hs) {
    const int tid = threadIdx.x;
    const int b0 = blockIdx.y * 64;
    const int j0 = blockIdx.x * 32;
    const __half* h1 = g_h[pin];
    const int lane = tid & 31, warp = tid >> 5;
    const int wm = warp >> 2, wn = warp & 3;
    const int g = lane >> 2, i2 = (lane & 3) * 2;
    const int lmA_row = lane & 15, lmA_koff = (lane >> 4) * 8;
    const int lmB_rowl = (lane >> 4) * 8 + (lane & 7);
    const int lmB_koff = ((lane >> 3) & 1) * 8;
    const int jb = j0 + wn * 8 + i2;

    // ---- prefetch epilogue operands (overlaps entire GEMM) ----
    float2 ereg[2][4], creg[2];
#pragma unroll
    for (int rs = 0; rs < 2; rs++) {
        int r = wm * 16 + g + rs * 8;
        int b = b0 + r;
        int tok = ids[b * Tz + t];
#pragma unroll
        for (int q = 0; q < 4; q++) {
            int n = q * Hz + jb;
            float2 e = *(const float2*)&E[(size_t)tok * G4z + n];
            if (use_zp) {
                float2 zp2 = *(const float2*)&g_zp[(size_t)b * G4z + n];
                e.x += zp2.x; e.y += zp2.y;
            }
            ereg[rs][q] = e;
        }
        creg[rs] = *(const float2*)&g_c[b * Hz + jb];
    }

    __half* Abase = smh;                 // [stage][64][LDK]
    __half* Bbase = smh + 3 * 64 * LDK;  // [stage][128][LDK]
#define A_ST(st) (Abase + (st) * 64 * LDK)
#define B_ST(st) (Bbase + (st) * 128 * LDK)

    auto stage_load = [&](int st, int k0) {
#pragma unroll
        for (int it = 0; it < 2; it++) {
            int c = tid + it * 512, r = c >> 4, kc8 = c & 15;
            cpa16(A_ST(st) + r * LDK + kc8 * 8, h1 + (size_t)(b0 + r) * Hz + k0 + kc8 * 8);
        }
#pragma unroll
        for (int it = 0; it < 4; it++) {
            int c = tid + it * 512, r = c >> 4, kc8 = c & 15;
            int q = (r >> 3) & 3, wnr = r >> 5, s = r & 7;
            size_t goff = (size_t)(q * Hz + j0 + wnr * 8 + s) * Hz + k0 + kc8 * 8;
            cpa16(B_ST(st) + r * LDK + kc8 * 8, U1 + goff);
        }
    };

    float acc[4][4] = {};
    stage_load(0, 0);   CP_COMMIT();
    stage_load(1, 128); CP_COMMIT();

    for (int kc = 0; kc < 4; kc++) {
        if (kc < 3) { CP_WAIT1(); } else { CP_WAIT0(); }
        __syncthreads();
        if (kc < 2) {
            stage_load((kc + 2) % 3, (kc + 2) * 128);
            CP_COMMIT();
        }
        const __half* A1 = A_ST(kc % 3);
        const __half* B1 = B_ST(kc % 3);
#pragma unroll
        for (int kk = 0; kk < 8; kk++) {
            int k = kk * 16;
            unsigned a1f[4], b1f[4][2];
            ldm_x4(a1f[0], a1f[1], a1f[2], a1f[3],
                   A1 + (wm * 16 + lmA_row) * LDK + k + lmA_koff);
#pragma unroll
            for (int q2 = 0; q2 < 2; q2++)
                ldm_x4(b1f[q2*2][0], b1f[q2*2][1], b1f[q2*2+1][0], b1f[q2*2+1][1],
                       B1 + (wn * 32 + q2 * 16 + lmB_rowl) * LDK + k + lmB_koff);
#pragma unroll
            for (int q = 0; q < 4; q++)
                mma16816(acc[q], a1f, b1f[q][0], b1f[q][1]);
        }
    }

    __half* o1 = g_h[pin ^ 1];
#pragma unroll
    for (int rs = 0; rs < 2; rs++) {
        int r = wm * 16 + g + rs * 8;
        int b = b0 + r;
        float2 gv[4];
#pragma unroll
        for (int q = 0; q < 4; q++)
            gv[q] = make_float2(acc[q][rs * 2 + 0] + ereg[rs][q].x,
                                acc[q][rs * 2 + 1] + ereg[rs][q].y);
        int idx = b * Hz + jb;
        float2 cold = creg[rs];
        float cn0 = sigm(gv[1].x) * cold.x + sigm(gv[0].x) * tanhf(gv[2].x);
        float cn1 = sigm(gv[1].y) * cold.y + sigm(gv[0].y) * tanhf(gv[2].y);
        float hn0 = sigm(gv[3].x) * tanhf(cn0);
        float hn1 = sigm(gv[3].y) * tanhf(cn1);
        *(float2*)&g_c[idx] = make_float2(cn0, cn1);
        __half2 hp = __halves2half2(__float2half_rn(hn0), __float2half_rn(hn1));
        *(__half2*)&o1[idx] = hp;
        if (store_hs)
            *(__half2*)&g_hs[((size_t)t * Bz + b) * Hz + jb] = hp;
    }
#undef A_ST
#undef B_ST
}

// ---------------- encoder step: BM=128 (both dirs), 1 wave ----------------
__global__ __launch_bounds__(512) void k_steph2(int t, int pin,
                                                const __half* __restrict__ U1a,
                                                const __half* __restrict__ U1b,
                                                const int* __restrict__ ids,
                                                const float* __restrict__ Ea,
                                                const float* __restrict__ Eb) {
    const int tid = threadIdx.x;
    const int by = blockIdx.y;
    const int dir = by >> 2;
    const int b0 = (by & 3) * 128;
    const int sb0 = dir * Bz + b0;
    const int j0 = blockIdx.x * 32;
    const __half* U1 = dir ? U1b : U1a;
    const float*  E  = dir ? Eb  : Ea;
    const __half* h1 = g_h[pin];
    const int lane = tid & 31, warp = tid >> 5;
    const int wm = warp >> 2, wn = warp & 3;
    const int g = lane >> 2, i2 = (lane & 3) * 2;
    const int lmA_row = lane & 15, lmA_koff = (lane >> 4) * 8;
    const int lmB_rowl = (lane >> 4) * 8 + (lane & 7);
    const int lmB_koff = ((lane >> 3) & 1) * 8;
    const int jb = j0 + wn * 8 + i2;
    const int tt = dir ? (Tz - 1 - t) : t;

    // ---- prefetch epilogue operands ----
    float2 ereg[2][2][4], creg[2][2];
#pragma unroll
    for (int mt = 0; mt < 2; mt++)
#pragma unroll
        for (int rs = 0; rs < 2; rs++) {
            int r = wm * 32 + mt * 16 + g + rs * 8;
            int tok = ids[(b0 + r) * Tz + tt];
#pragma unroll
            for (int q = 0; q < 4; q++)
                ereg[mt][rs][q] = *(const float2*)&E[(size_t)tok * G4z + q * Hz + jb];
            creg[mt][rs] = *(const float2*)&g_c[(sb0 + r) * Hz + jb];
        }

    __half* Abase = smh;                  // [stage][128][LDK]
    __half* Bbase = smh + 3 * 128 * LDK;  // [stage][128][LDK]
#define A2_ST(st) (Abase + (st) * 128 * LDK)
#define B2_ST(st) (Bbase + (st) * 128 * LDK)

    auto stage_load = [&](int st, int k0) {
#pragma unroll
        for (int it = 0; it < 4; it++) {
            int c = tid + it * 512, r = c >> 4, kc8 = c & 15;
            cpa16(A2_ST(st) + r * LDK + kc8 * 8, h1 + (size_t)(sb0 + r) * Hz + k0 + kc8 * 8);
        }
#pragma unroll
        for (int it = 0; it < 4; it++) {
            int c = tid + it * 512, r = c >> 4, kc8 = c & 15;
            int q = (r >> 3) & 3, wnr = r >> 5, s = r & 7;
            size_t goff = (size_t)(q * Hz + j0 + wnr * 8 + s) * Hz + k0 + kc8 * 8;
            cpa16(B2_ST(st) + r * LDK + kc8 * 8, U1 + goff);
        }
    };

    float acc[2][4][4] = {};
    stage_load(0, 0);   CP_COMMIT();
    stage_load(1, 128); CP_COMMIT();

    for (int kc = 0; kc < 4; kc++) {
        if (kc < 3) { CP_WAIT1(); } else { CP_WAIT0(); }
        __syncthreads();
        if (kc < 2) {
            stage_load((kc + 2) % 3, (kc + 2) * 128);
            CP_COMMIT();
        }
        const __half* A1 = A2_ST(kc % 3);
        const __half* B1 = B2_ST(kc % 3);
#pragma unroll
        for (int kk = 0; kk < 8; kk++) {
            int k = kk * 16;
            unsigned a1f[2][4], b1f[4][2];
#pragma unroll
            for (int mt = 0; mt < 2; mt++)
                ldm_x4(a1f[mt][0], a1f[mt][1], a1f[mt][2], a1f[mt][3],
                       A1 + (wm * 32 + mt * 16 + lmA_row) * LDK + k + lmA_koff);
#pragma unroll
            for (int q2 = 0; q2 < 2; q2++)
                ldm_x4(b1f[q2*2][0], b1f[q2*2][1], b1f[q2*2+1][0], b1f[q2*2+1][1],
                       B1 + (wn * 32 + q2 * 16 + lmB_rowl) * LDK + k + lmB_koff);
#pragma unroll
            for (int mt = 0; mt < 2; mt++)
#pragma unroll
                for (int q = 0; q < 4; q++)
                    mma16816(acc[mt][q], a1f[mt], b1f[q][0], b1f[q][1]);
        }
    }

    __half* o1 = g_h[pin ^ 1];
#pragma unroll
    for (int mt = 0; mt < 2; mt++)
#pragma unroll
        for (int rs = 0; rs < 2; rs++) {
            int r = wm * 32 + mt * 16 + g + rs * 8;
            int sb = sb0 + r;
            float2 gv[4];
#pragma unroll
            for (int q = 0; q < 4; q++)
                gv[q] = make_float2(acc[mt][q][rs * 2 + 0] + ereg[mt][rs][q].x,
                                    acc[mt][q][rs * 2 + 1] + ereg[mt][rs][q].y);
            int idx = sb * Hz + jb;
            float2 cold = creg[mt][rs];
            float cn0 = sigm(gv[1].x) * cold.x + sigm(gv[0].x) * tanhf(gv[2].x);
            float cn1 = sigm(gv[1].y) * cold.y + sigm(gv[0].y) * tanhf(gv[2].y);
            float hn0 = sigm(gv[3].x) * tanhf(cn0);
            float hn1 = sigm(gv[3].y) * tanhf(cn1);
            *(float2*)&g_c[idx] = make_float2(cn0, cn1);
            *(__half2*)&o1[idx] =
                __halves2half2(__float2half_rn(hn0), __float2half_rn(hn1));
        }
#undef A2_ST
#undef B2_ST
}

// ---------------- output head: 1-MMA mma.sync ----------------
__global__ __launch_bounds__(256) void k_outheadh(const float* __restrict__ bout,
                                                  float* __restrict__ out) {
    __half* A1 = smh;
    __half* B1 = smh + 64 * LDA;
    const int tid = threadIdx.x;
    const int m0 = blockIdx.x * 64;
    const int lane = tid & 31, warp = tid >> 5;
    const int wm = warp >> 2, wn = warp & 3;
    const int g = lane >> 2, i2 = (lane & 3) * 2;
    float acc[2][2][4] = {};

    for (int kc = 0; kc < 8; kc++) {
        int k0 = kc * 64;
        __syncthreads();
#pragma unroll
        for (int it = 0; it < 2; it++) {
            int c = tid + it * 256, r = c >> 3, col = (c & 7) * 8;
            *(uint4*)(A1 + r * LDA + col) = *(const uint4*)(g_hs + (size_t)(m0 + r) * Hz + k0 + col);
            *(uint4*)(B1 + r * LDB + col) = *(const uint4*)(g_Wo + (size_t)r * Hz + k0 + col);
        }
        __syncthreads();
#pragma unroll
        for (int kk = 0; kk < 4; kk++) {
            int k = kk * 16;
            unsigned a1f[2][4], b1f[2][2];
#pragma unroll
            for (int mt = 0; mt < 2; mt++) {
                int rbase = (wm * 32 + mt * 16 + g) * LDA + k + i2;
                load_afrag(a1f[mt], A1, rbase);
            }
#pragma unroll
            for (int nt = 0; nt < 2; nt++) {
                int rb = (wn * 16 + nt * 8 + g) * LDB + k + i2;
                b1f[nt][0] = *(const unsigned*)(B1 + rb);
                b1f[nt][1] = *(const unsigned*)(B1 + rb + 8);
            }
#pragma unroll
            for (int mt = 0; mt < 2; mt++)
#pragma unroll
                for (int nt = 0; nt < 2; nt++)
                    mma16816(acc[mt][nt], a1f[mt], b1f[nt][0], b1f[nt][1]);
        }
    }
#pragma unroll
    for (int mt = 0; mt < 2; mt++)
#pragma unroll
        for (int rs = 0; rs < 2; rs++)
#pragma unroll
            for (int jj = 0; jj < 2; jj++) {
                int m = m0 + wm * 32 + mt * 16 + g + rs * 8;
                int b = m & (Bz - 1), tt = m >> 9;
                int ci = rs * 2 + jj;
#pragma unroll
                for (int nt = 0; nt < 2; nt++) {
                    int v = wn * 16 + nt * 8 + i2 + jj;
                    out[((size_t)b * Tz + tt) * Vz + v] = acc[mt][nt][ci] + bout[v];
                }
            }
}

// ---------------- launch ----------------
extern "C" void kernel_launch(void* const* d_in, const int* in_sizes, int n_in,
                              void* d_out, int out_size) {
    const int* x   = (const int*)d_in[0];
    const int* tgt = (const int*)d_in[1];
    const float* eps   = (const float*)d_in[2];
    const float* emb   = (const float*)d_in[3];
    const float* Wih_f = (const float*)d_in[4];
    const float* Whh_f = (const float*)d_in[5];
    const float* b_f   = (const float*)d_in[6];
    const float* Wih_b = (const float*)d_in[7];
    const float* Whh_b = (const float*)d_in[8];
    const float* b_b   = (const float*)d_in[9];
    const float* W_mu  = (const float*)d_in[10];
    const float* b_mu  = (const float*)d_in[11];
    const float* W_lv  = (const float*)d_in[12];
    const float* b_lv  = (const float*)d_in[13];
    const float* W_di  = (const float*)d_in[14];
    const float* b_di  = (const float*)d_in[15];
    const float* Wih_d = (const float*)d_in[16];
    const float* Whh_d = (const float*)d_in[17];
    const float* b_d   = (const float*)d_in[18];
    const float* W_out = (const float*)d_in[19];
    const float* b_out = (const float*)d_in[20];

    float* out  = (float*)d_out;
    float* mu_o = out + (size_t)Bz * Tz * Vz;
    float* lv_o = mu_o + Bz * Lz;

    cudaFuncSetAttribute(k_steph,    cudaFuncAttributeMaxDynamicSharedMemorySize, SMEM_D);
    cudaFuncSetAttribute(k_steph2,   cudaFuncAttributeMaxDynamicSharedMemorySize, SMEM_E);
    cudaFuncSetAttribute(k_outheadh, cudaFuncAttributeMaxDynamicSharedMemorySize, SMEM_OUT);

    __half *uf, *ub, *ud;
    float *ef, *eb, *ed, *hcat, *z, *zp, *htmp;
    cudaGetSymbolAddress((void**)&uf, g_Uf);
    cudaGetSymbolAddress((void**)&ub, g_Ub);
    cudaGetSymbolAddress((void**)&ud, g_Ud);
    cudaGetSymbolAddress((void**)&ef, g_EF);
    cudaGetSymbolAddress((void**)&eb, g_EB);
    cudaGetSymbolAddress((void**)&ed, g_ED);
    cudaGetSymbolAddress((void**)&hcat, g_hcat);
    cudaGetSymbolAddress((void**)&z, g_z);
    cudaGetSymbolAddress((void**)&zp, g_zp);
    cudaGetSymbolAddress((void**)&htmp, g_htmp);

    dim3 encGrid(Hz / 32, 8);    // 128 CTAs, both dirs, 1 wave
    dim3 decGrid(Hz / 32, 8);    // 128 CTAs
    int zeroBlocks2 = (2 * Bz * Hz + 255) / 256;
    int zeroBlocks1 = (Bz * Hz + 255) / 256;

    // ---- fused prologue ----
    k_cvt_all<<<1024, 256>>>(Whh_f, Whh_b, Whh_d, W_out);
    k_tables<<<dim3(32, 3), 256>>>(emb, Wih_f, b_f, Wih_b, b_b, Wih_d, b_d);
    k_zero_state<<<zeroBlocks2, 256>>>();

    // ---- encoder (both directions, BM=128) ----
    for (int t = 0; t < Tz; t++)
        k_steph2<<<encGrid, 512, SMEM_E>>>(t, t & 1, uf, ub, x, ef, eb);
    k_copy_hcat<<<zeroBlocks2, 256>>>();

    // ---- latent heads + reparameterize ----
    k_gemm<<<dim3(Lz / 64, Bz / 64), 256>>>(2 * Hz, hcat, 2 * Hz, W_mu, 2 * Hz, b_mu, mu_o, Lz);
    k_gemm<<<dim3(Lz / 64, Bz / 64), 256>>>(2 * Hz, hcat, 2 * Hz, W_lv, 2 * Hz, b_lv, lv_o, Lz);
    k_reparam<<<(Bz * Lz + 255) / 256, 256>>>(eps, mu_o, lv_o);

    // ---- decoder prologue ----
    k_gemm<<<dim3(G4z / 64, Bz / 64), 256>>>(Lz, z, Lz, Wih_d + Ez, ELz, nullptr, zp, G4z);
    k_gemm<<<dim3(Hz / 64, Bz / 64), 256>>>(Lz, z, Lz, W_di, Lz, b_di, htmp, Hz);
    k_hd_init<<<zeroBlocks1, 256>>>();

    // ---- decoder recurrence ----
    for (int t = 0; t < Tz; t++)
        k_steph<<<decGrid, 512, SMEM_D>>>(t, t & 1, ud, tgt, ed, 1, 1);

    // ---- output head ----
    k_outheadh<<<(Tz * Bz) / 64, 256, SMEM_OUT>>>(b_out, out);
}